// round 1
// baseline (speedup 1.0000x reference)
#include <cuda_runtime.h>
#include <cuda_bf16.h>
#include <math.h>

// Problem constants
#define BB   4
#define HH   16
#define SS   1024
#define DKK  64
#define TQ   32      // query rows per CTA
#define TK   128     // key cols per K tile
#define NTHREADS 256
#define NEGV (-1.0e9f)

// SMEM layout (floats):
//   sQt[64][32]    : Q tile, d-major             ( 2048 floats,   8 KB)
//   sKt[64][128]   : K tile, d-major             ( 8192 floats,  32 KB)
//   sS [32][1024]  : score tile                  (32768 floats, 128 KB)
#define OFF_QT 0
#define OFF_KT 2048
#define OFF_S  10240
#define SMEM_FLOATS (OFF_S + TQ * SS)
#define SMEM_BYTES  (SMEM_FLOATS * 4)

__global__ void __launch_bounds__(NTHREADS, 1)
mha_fused_kernel(const float* __restrict__ Q,
                 const float* __restrict__ K,
                 const int*   __restrict__ M,
                 float* __restrict__ attn_out,
                 float* __restrict__ scores_out)
{
    extern __shared__ float smem[];
    float* sQt = smem + OFF_QT;   // [d][q]  : d*32 + q
    float* sKt = smem + OFF_KT;   // [d][k]  : d*128 + k
    float* sS  = smem + OFF_S;    // [q][k]  : q*1024 + k

    const int tid = threadIdx.x;
    const int qt  = blockIdx.x;           // 0..31
    const int h   = blockIdx.y;           // 0..15
    const int b   = blockIdx.z;           // 0..3
    const int q0  = qt * TQ;

    const float* Qp = Q + ((size_t)(b * HH + h) * SS + q0) * DKK;
    const float* Kp = K + (size_t)(b * HH + h) * SS * DKK;
    const int*   Mp = M + ((size_t)b * SS + q0) * SS;
    const size_t obase = ((size_t)(b * HH + h) * SS + q0) * SS;

    // ---- load Q tile transposed: sQt[d][q] ----
    // 32 q * 16 float4 = 512 float4 ; 2 per thread
    #pragma unroll
    for (int i = 0; i < 2; i++) {
        int idx = tid + i * NTHREADS;
        int qq  = idx >> 4;
        int d4  = idx & 15;
        float4 v = reinterpret_cast<const float4*>(Qp + (size_t)qq * DKK)[d4];
        sQt[(4 * d4 + 0) * TQ + qq] = v.x;
        sQt[(4 * d4 + 1) * TQ + qq] = v.y;
        sQt[(4 * d4 + 2) * TQ + qq] = v.z;
        sQt[(4 * d4 + 3) * TQ + qq] = v.w;
    }

    const int qg = tid >> 5;   // 0..7  -> q micro-tile base 4*qg
    const int kg = tid & 31;   // 0..31 -> k micro-tile base 4*kg

    // ---- GEMM over K tiles ----
    for (int kt = 0; kt < SS; kt += TK) {
        __syncthreads();   // previous tile's sKt fully consumed
        // load K tile transposed: 128 k * 16 float4 = 2048 float4 ; 8 per thread
        #pragma unroll
        for (int i = 0; i < 8; i++) {
            int idx = tid + i * NTHREADS;
            int kk  = idx >> 4;
            int d4  = idx & 15;
            float4 v = reinterpret_cast<const float4*>(Kp + (size_t)(kt + kk) * DKK)[d4];
            sKt[(4 * d4 + 0) * TK + kk] = v.x;
            sKt[(4 * d4 + 1) * TK + kk] = v.y;
            sKt[(4 * d4 + 2) * TK + kk] = v.z;
            sKt[(4 * d4 + 3) * TK + kk] = v.w;
        }
        __syncthreads();

        float acc[4][4];
        #pragma unroll
        for (int i = 0; i < 4; i++)
            #pragma unroll
            for (int j = 0; j < 4; j++)
                acc[i][j] = 0.0f;

        #pragma unroll
        for (int d = 0; d < DKK; d++) {
            float4 a = *reinterpret_cast<const float4*>(&sQt[d * TQ + 4 * qg]);
            float4 bv = *reinterpret_cast<const float4*>(&sKt[d * TK + 4 * kg]);
            acc[0][0] += a.x * bv.x; acc[0][1] += a.x * bv.y;
            acc[0][2] += a.x * bv.z; acc[0][3] += a.x * bv.w;
            acc[1][0] += a.y * bv.x; acc[1][1] += a.y * bv.y;
            acc[1][2] += a.y * bv.z; acc[1][3] += a.y * bv.w;
            acc[2][0] += a.z * bv.x; acc[2][1] += a.z * bv.y;
            acc[2][2] += a.z * bv.z; acc[2][3] += a.z * bv.w;
            acc[3][0] += a.w * bv.x; acc[3][1] += a.w * bv.y;
            acc[3][2] += a.w * bv.z; acc[3][3] += a.w * bv.w;
        }

        #pragma unroll
        for (int i = 0; i < 4; i++) {
            float4 st = make_float4(acc[i][0], acc[i][1], acc[i][2], acc[i][3]);
            *reinterpret_cast<float4*>(&sS[(4 * qg + i) * SS + kt + 4 * kg]) = st;
        }
    }
    __syncthreads();

    // ---- scale + mask pass (coalesced), also emit scores ----
    const float scale = 0.125f;   // 1/sqrt(64)
    float4*       sS4 = reinterpret_cast<float4*>(sS);
    const int4*   M4  = reinterpret_cast<const int4*>(Mp);
    float4*       SO4 = reinterpret_cast<float4*>(scores_out + obase);
    #pragma unroll
    for (int i = 0; i < (TQ * SS / 4) / NTHREADS; i++) {   // 32 iters
        int idx = tid + i * NTHREADS;
        float4 s = sS4[idx];
        int4   m = M4[idx];
        s.x = m.x ? s.x * scale : NEGV;
        s.y = m.y ? s.y * scale : NEGV;
        s.z = m.z ? s.z * scale : NEGV;
        s.w = m.w ? s.w * scale : NEGV;
        sS4[idx] = s;
        SO4[idx] = s;
    }
    __syncthreads();

    // ---- softmax: warp per row, 4 rows per warp ----
    const int warp = tid >> 5;
    const int lane = tid & 31;
    #pragma unroll
    for (int r = 0; r < 4; r++) {
        const int q = warp * 4 + r;
        const float4* row = reinterpret_cast<const float4*>(&sS[q * SS]);
        float4 vv[8];
        float mx = -INFINITY;
        #pragma unroll
        for (int j = 0; j < 8; j++) {
            vv[j] = row[lane + j * 32];
            mx = fmaxf(mx, fmaxf(fmaxf(vv[j].x, vv[j].y), fmaxf(vv[j].z, vv[j].w)));
        }
        #pragma unroll
        for (int o = 16; o > 0; o >>= 1)
            mx = fmaxf(mx, __shfl_xor_sync(0xFFFFFFFFu, mx, o));

        float sum = 0.0f;
        #pragma unroll
        for (int j = 0; j < 8; j++) {
            vv[j].x = __expf(vv[j].x - mx);
            vv[j].y = __expf(vv[j].y - mx);
            vv[j].z = __expf(vv[j].z - mx);
            vv[j].w = __expf(vv[j].w - mx);
            sum += vv[j].x + vv[j].y + vv[j].z + vv[j].w;
        }
        #pragma unroll
        for (int o = 16; o > 0; o >>= 1)
            sum += __shfl_xor_sync(0xFFFFFFFFu, sum, o);

        const float inv = 1.0f / sum;
        float4* ao = reinterpret_cast<float4*>(attn_out + obase + (size_t)q * SS);
        #pragma unroll
        for (int j = 0; j < 8; j++) {
            float4 e = vv[j];
            e.x *= inv; e.y *= inv; e.z *= inv; e.w *= inv;
            ao[lane + j * 32] = e;
        }
    }
}

extern "C" void kernel_launch(void* const* d_in, const int* in_sizes, int n_in,
                              void* d_out, int out_size)
{
    const float* Q = (const float*)d_in[0];
    const float* K = (const float*)d_in[1];
    // d_in[2] = value : unused by (attn, scores) outputs
    const int*   M = (const int*)d_in[3];

    float* attn   = (float*)d_out;                                  // first half
    float* scores = (float*)d_out + (size_t)BB * HH * SS * SS;      // second half

    cudaFuncSetAttribute(mha_fused_kernel,
                         cudaFuncAttributeMaxDynamicSharedMemorySize, SMEM_BYTES);

    dim3 grid(SS / TQ, HH, BB);   // (32, 16, 4)
    mha_fused_kernel<<<grid, NTHREADS, SMEM_BYTES>>>(Q, K, M, attn, scores);
}

// round 3
// speedup vs baseline: 2.0970x; 2.0970x over previous
#include <cuda_runtime.h>
#include <cuda_bf16.h>
#include <math.h>
#include <stdint.h>

#define BB 4
#define HH 16
#define SSEQ 1024
#define DKD 64
#define TQ 64
#define NT 256
#define NEGV (-1.0e9f)
#define SCALE 0.125f
#define PADB 144            // bf16 row: 64*2=128B padded to 144B (36 words -> conflict-free)

#define OFF_QHI 0
#define OFF_QLO (TQ * PADB)                 //  9216
#define OFF_KHI (2 * TQ * PADB)             // 18432
#define OFF_KLO (OFF_KHI + 128 * PADB)      // 36864
#define OFF_RED (OFF_KLO + 128 * PADB)      // 55296
#define SMEM_TOTAL (OFF_RED + (128 + 64) * 4)  // 56064 bytes

__device__ __forceinline__ uint32_t pack_bf2(__nv_bfloat16 a, __nv_bfloat16 b) {
    return (uint32_t)__bfloat16_as_ushort(a) | ((uint32_t)__bfloat16_as_ushort(b) << 16);
}

__device__ __forceinline__ void mma_bf16(float* d,
                                         uint32_t a0, uint32_t a1, uint32_t a2, uint32_t a3,
                                         uint32_t b0, uint32_t b1) {
    asm volatile(
        "mma.sync.aligned.m16n8k16.row.col.f32.bf16.bf16.f32 "
        "{%0,%1,%2,%3}, {%4,%5,%6,%7}, {%8,%9}, {%0,%1,%2,%3};"
        : "+f"(d[0]), "+f"(d[1]), "+f"(d[2]), "+f"(d[3])
        : "r"(a0), "r"(a1), "r"(a2), "r"(a3), "r"(b0), "r"(b1));
}

__global__ void __launch_bounds__(NT, 2)
mha_fused(const float* __restrict__ Q, const float* __restrict__ K,
          const int* __restrict__ M,
          float* __restrict__ attn, float* __restrict__ scores)
{
    extern __shared__ char sm[];
    char*  sQhi = sm + OFF_QHI;
    char*  sQlo = sm + OFF_QLO;
    char*  sKhi = sm + OFF_KHI;
    char*  sKlo = sm + OFF_KLO;
    float* sred = (float*)(sm + OFF_RED);   // [128] partial row sums
    float* sinv = sred + 128;               // [64]  1/rowsum

    const int tid  = threadIdx.x;
    const int lane = tid & 31;
    const int wid  = tid >> 5;
    const int wq   = wid >> 1;              // 0..3 : q subtile (16 rows)
    const int wk   = wid & 1;               // 0..1 : k half (64 cols)
    const int qt = blockIdx.x, h = blockIdx.y, b = blockIdx.z;
    const int q0 = qt * TQ;

    const float* Qp = Q + ((size_t)(b * HH + h) * SSEQ + q0) * DKD;
    const float* Kp = K + (size_t)(b * HH + h) * SSEQ * DKD;
    const int*   Mp = M + ((size_t)b * SSEQ + q0) * SSEQ;
    float*       Sp = scores + ((size_t)(b * HH + h) * SSEQ + q0) * SSEQ;
    float*       Ap = attn   + ((size_t)(b * HH + h) * SSEQ + q0) * SSEQ;

    // ---- convert Q tile fp32 -> bf16 hi/lo (padded rows) ----
    #pragma unroll
    for (int i = 0; i < 4; i++) {
        int idx = tid + i * NT;             // 1024 float4 groups
        int row = idx >> 4, c4 = idx & 15;
        float4 v = reinterpret_cast<const float4*>(Qp + (size_t)row * DKD)[c4];
        __nv_bfloat16 bx = __float2bfloat16_rn(v.x), by = __float2bfloat16_rn(v.y);
        __nv_bfloat16 bz = __float2bfloat16_rn(v.z), bw = __float2bfloat16_rn(v.w);
        uint2 hi = make_uint2(pack_bf2(bx, by), pack_bf2(bz, bw));
        uint2 lo = make_uint2(
            pack_bf2(__float2bfloat16_rn(v.x - __bfloat162float(bx)),
                     __float2bfloat16_rn(v.y - __bfloat162float(by))),
            pack_bf2(__float2bfloat16_rn(v.z - __bfloat162float(bz)),
                     __float2bfloat16_rn(v.w - __bfloat162float(bw))));
        *reinterpret_cast<uint2*>(sQhi + row * PADB + c4 * 8) = hi;
        *reinterpret_cast<uint2*>(sQlo + row * PADB + c4 * 8) = lo;
    }

    const int rA  = wq * 16 + (lane >> 2);   // A fragment row (local)
    const int cb  = 4 * (lane & 3);          // byte offset within 32B k-step block
    const int rB0 = wk * 64 + (lane >> 2);   // B fragment base row (local to k tile)

    float sumE0 = 0.0f, sumE1 = 0.0f;

    for (int kt = 0; kt < SSEQ; kt += 128) {
        __syncthreads();   // previous K tile fully consumed

        // ---- convert K tile (128 rows) ----
        #pragma unroll
        for (int i = 0; i < 8; i++) {
            int idx = tid + i * NT;          // 2048 float4 groups
            int row = idx >> 4, c4 = idx & 15;
            float4 v = reinterpret_cast<const float4*>(Kp + (size_t)(kt + row) * DKD)[c4];
            __nv_bfloat16 bx = __float2bfloat16_rn(v.x), by = __float2bfloat16_rn(v.y);
            __nv_bfloat16 bz = __float2bfloat16_rn(v.z), bw = __float2bfloat16_rn(v.w);
            uint2 hi = make_uint2(pack_bf2(bx, by), pack_bf2(bz, bw));
            uint2 lo = make_uint2(
                pack_bf2(__float2bfloat16_rn(v.x - __bfloat162float(bx)),
                         __float2bfloat16_rn(v.y - __bfloat162float(by))),
                pack_bf2(__float2bfloat16_rn(v.z - __bfloat162float(bz)),
                         __float2bfloat16_rn(v.w - __bfloat162float(bw))));
            *reinterpret_cast<uint2*>(sKhi + row * PADB + c4 * 8) = hi;
            *reinterpret_cast<uint2*>(sKlo + row * PADB + c4 * 8) = lo;
        }
        __syncthreads();

        float acc[8][4];
        #pragma unroll
        for (int n = 0; n < 8; n++)
            #pragma unroll
            for (int j = 0; j < 4; j++)
                acc[n][j] = 0.0f;

        // ---- 16x128 GEMM per warp via m16n8k16, 3-way hi/lo split ----
        #pragma unroll
        for (int s = 0; s < 4; s++) {
            const char* qh = sQhi + rA * PADB + s * 32 + cb;
            const char* ql = sQlo + rA * PADB + s * 32 + cb;
            uint32_t ah0 = *(const uint32_t*)qh;
            uint32_t ah1 = *(const uint32_t*)(qh + 8 * PADB);
            uint32_t ah2 = *(const uint32_t*)(qh + 16);
            uint32_t ah3 = *(const uint32_t*)(qh + 8 * PADB + 16);
            uint32_t al0 = *(const uint32_t*)ql;
            uint32_t al1 = *(const uint32_t*)(ql + 8 * PADB);
            uint32_t al2 = *(const uint32_t*)(ql + 16);
            uint32_t al3 = *(const uint32_t*)(ql + 8 * PADB + 16);
            #pragma unroll
            for (int nt = 0; nt < 8; nt++) {
                const char* kh = sKhi + (rB0 + nt * 8) * PADB + s * 32 + cb;
                const char* kl = sKlo + (rB0 + nt * 8) * PADB + s * 32 + cb;
                uint32_t bh0 = *(const uint32_t*)kh;
                uint32_t bh1 = *(const uint32_t*)(kh + 16);
                uint32_t bl0 = *(const uint32_t*)kl;
                uint32_t bl1 = *(const uint32_t*)(kl + 16);
                mma_bf16(acc[nt], ah0, ah1, ah2, ah3, bh0, bh1);
                mma_bf16(acc[nt], ah0, ah1, ah2, ah3, bl0, bl1);
                mma_bf16(acc[nt], al0, al1, al2, al3, bh0, bh1);
            }
        }

        // ---- epilogue: mask+scale, write scores, accumulate exp sums ----
        const int r0l = wq * 16 + (lane >> 2);
        #pragma unroll
        for (int nt = 0; nt < 8; nt++) {
            int kc = kt + wk * 64 + nt * 8 + 2 * (lane & 3);
            int2 m0 = *reinterpret_cast<const int2*>(Mp + (size_t)r0l * SSEQ + kc);
            int2 m1 = *reinterpret_cast<const int2*>(Mp + (size_t)(r0l + 8) * SSEQ + kc);
            float s0 = m0.x ? acc[nt][0] * SCALE : NEGV;
            float s1 = m0.y ? acc[nt][1] * SCALE : NEGV;
            float s2 = m1.x ? acc[nt][2] * SCALE : NEGV;
            float s3 = m1.y ? acc[nt][3] * SCALE : NEGV;
            sumE0 += __expf(s0) + __expf(s1);
            sumE1 += __expf(s2) + __expf(s3);
            *reinterpret_cast<float2*>(Sp + (size_t)r0l * SSEQ + kc)       = make_float2(s0, s1);
            *reinterpret_cast<float2*>(Sp + (size_t)(r0l + 8) * SSEQ + kc) = make_float2(s2, s3);
        }
    }

    // ---- row-sum reduction: 4 lanes per row, then across the two k-half warps ----
    sumE0 += __shfl_xor_sync(0xFFFFFFFFu, sumE0, 1);
    sumE0 += __shfl_xor_sync(0xFFFFFFFFu, sumE0, 2);
    sumE1 += __shfl_xor_sync(0xFFFFFFFFu, sumE1, 1);
    sumE1 += __shfl_xor_sync(0xFFFFFFFFu, sumE1, 2);
    if ((lane & 3) == 0) {
        int r0l = wq * 16 + (lane >> 2);
        sred[wk * 64 + r0l]     = sumE0;
        sred[wk * 64 + r0l + 8] = sumE1;
    }
    __syncthreads();
    if (tid < 64) sinv[tid] = 1.0f / (sred[tid] + sred[64 + tid]);
    __syncthreads();

    // ---- fused attn pass: re-read scores (L2-hot), scale by 1/rowsum ----
    #pragma unroll 8
    for (int i = 0; i < 64; i++) {
        int idx = tid + i * NT;              // 16384 float4 = 64 rows x 256
        int row = idx >> 8;
        float inv = sinv[row];
        float4 s = reinterpret_cast<const float4*>(Sp)[idx];
        float4 a;
        a.x = __expf(s.x) * inv;
        a.y = __expf(s.y) * inv;
        a.z = __expf(s.z) * inv;
        a.w = __expf(s.w) * inv;
        reinterpret_cast<float4*>(Ap)[idx] = a;
    }
}

extern "C" void kernel_launch(void* const* d_in, const int* in_sizes, int n_in,
                              void* d_out, int out_size)
{
    const float* Q = (const float*)d_in[0];
    const float* K = (const float*)d_in[1];
    const int*   M = (const int*)d_in[3];    // d_in[2] = value, unused by outputs

    float* attn   = (float*)d_out;
    float* scores = (float*)d_out + (size_t)BB * HH * SSEQ * SSEQ;

    cudaFuncSetAttribute(mha_fused, cudaFuncAttributeMaxDynamicSharedMemorySize, SMEM_TOTAL);

    dim3 grid(SSEQ / TQ, HH, BB);            // (16,16,4) = 1024 CTAs
    mha_fused<<<grid, NT, SMEM_TOTAL>>>(Q, K, M, attn, scores);
}